// round 14
// baseline (speedup 1.0000x reference)
#include <cuda_runtime.h>
#include <cuda_fp16.h>
#include <cstdint>
#include <math.h>

#define BATCH 16
#define NMASK 6
#define HW 1089
#define DIM 512
#define NLBL 7
#define INV_T (1.0f/0.07f)
#define SEPM 2.0f
#define UNITH 0.1f

#define CTILES 9          // ceil(1089/128)
#define NTILEPAIRS 45     // CTILES*(CTILES+1)/2
#define NPD 29            // 28 pair-dots + ||mean_all||^2

// ---- smem layout for supcon_mma (dynamic) ----
#define SM_ROWS 0                 // 128 floats (row S accum)
#define SM_COLS 512               // 128 floats (col S accum)
#define SM_BUF  1024
#define MATSZ   16384             // 128 rows x 64 fp16 (128B/row)
#define STAGESZ (2*MATSZ)         // A,B = 32KB
#define NSTAGE  3
#define SM_TOTAL (SM_BUF + NSTAGE*STAGESZ)   // 99328 -> 2 CTAs/SM

// ---- scratch (device globals: allocation-free) ----
__device__ float g_label_sums[BATCH][NLBL][DIM];
__device__ float g_cnt[BATCH][NLBL];
__device__ float g_supcon_sum[BATCH];
__device__ float g_anchor_cnt[BATCH];
__device__ float g_pd[BATCH][NPD];
__device__ int   g_active[BATCH * NMASK];
__device__ int   g_labels[BATCH * HW];
__device__ float g_S[BATCH * HW];
__device__ __align__(16) __half g_h[(size_t)BATCH * HW * DIM];

// ================= helpers =================
__device__ __forceinline__ uint32_t smem_u32(const void* p) {
    uint32_t a;
    asm("{ .reg .u64 t; cvta.to.shared.u64 t, %1; cvt.u32.u64 %0, t; }" : "=r"(a) : "l"(p));
    return a;
}
__device__ __forceinline__ void ldsm4(uint32_t* r, uint32_t addr) {
    asm volatile("ldmatrix.sync.aligned.m8n8.x4.shared.b16 {%0,%1,%2,%3}, [%4];"
                 : "=r"(r[0]), "=r"(r[1]), "=r"(r[2]), "=r"(r[3]) : "r"(addr));
}
__device__ __forceinline__ void mma_f16(float* c, const uint32_t* a, const uint32_t* b) {
    asm volatile("mma.sync.aligned.m16n8k16.row.col.f32.f16.f16.f32 "
                 "{%0,%1,%2,%3}, {%4,%5,%6,%7}, {%8,%9}, {%0,%1,%2,%3};"
                 : "+f"(c[0]), "+f"(c[1]), "+f"(c[2]), "+f"(c[3])
                 : "r"(a[0]), "r"(a[1]), "r"(a[2]), "r"(a[3]), "r"(b[0]), "r"(b[1]));
}
__device__ __forceinline__ int PD(int a, int c) { return a * 7 - (a * (a + 1)) / 2 + c; }

// Fast exp on FMA/ALU pipes (no MUFU): mean-one-tuned Schraudolph.
__device__ __forceinline__ float fexp(float x) {
    return __int_as_float((int)(fmaf(x, 12102203.0f, 1064870693.0f)));
}

// ---------------------------------------------------------------------------
// fused prep + zero + cvt:
//   blocks [0,96): mask-channel active flags
//   blocks [96,320): zero accumulators
//   blocks [320,4676): streaming fp32 -> fp16 conversion (rn2 == 1 exactly)
// ---------------------------------------------------------------------------
#define ZBLK 224
#define PBLK (BATCH * NMASK + ZBLK)               // 320
#define CVTBLK ((BATCH * HW * DIM) / (256 * 8))   // 4356
__global__ void prepcvt_kernel(const float* __restrict__ masks,
                               const float* __restrict__ emb) {
    int blk = blockIdx.x;
    if (blk < BATCH * NMASK) {
        const float* m = masks + (size_t)blk * HW;
        float s = 0.f;
        for (int i = threadIdx.x; i < HW; i += blockDim.x) s += m[i];
        __shared__ float sh[256];
        sh[threadIdx.x] = s;
        __syncthreads();
        for (int o = 128; o > 0; o >>= 1) {
            if (threadIdx.x < o) sh[threadIdx.x] += sh[threadIdx.x + o];
            __syncthreads();
        }
        if (threadIdx.x == 0) g_active[blk] = (sh[0] > 0.f) ? 1 : 0;
    } else if (blk < PBLK) {
        int i = (blk - BATCH * NMASK) * 256 + threadIdx.x;
        if (i < BATCH * HW) g_S[i] = 0.f;
        if (i < BATCH * NLBL * DIM) ((float*)g_label_sums)[i] = 0.f;
        if (i < BATCH * NLBL) ((float*)g_cnt)[i] = 0.f;
    } else {
        size_t i = ((size_t)(blk - PBLK) * 256 + threadIdx.x) * 8;
        float4 v0 = *(const float4*)(emb + i);
        float4 v1 = *(const float4*)(emb + i + 4);
        __half hh[8];
        hh[0] = __float2half(v0.x); hh[1] = __float2half(v0.y);
        hh[2] = __float2half(v0.z); hh[3] = __float2half(v0.w);
        hh[4] = __float2half(v1.x); hh[5] = __float2half(v1.y);
        hh[6] = __float2half(v1.z); hh[7] = __float2half(v1.w);
        *(uint4*)(g_h + i) = *(uint4*)hh;
    }
}

// ---------------------------------------------------------------------------
// labels
// ---------------------------------------------------------------------------
__global__ void labels_kernel(const float* __restrict__ masks) {
    int idx = blockIdx.x * blockDim.x + threadIdx.x;
    if (idx >= BATCH * HW) return;
    int b = idx / HW, n = idx - b * HW;
    const float* mb = masks + (size_t)b * NMASK * HW;
    int lbl = 0;
#pragma unroll
    for (int m = 0; m < NMASK; m++) {
        if (mb[(size_t)m * HW + n] > 0.5f && g_active[b * NMASK + m]) lbl = m + 1;
    }
    g_labels[idx] = lbl;
}

// ---------------------------------------------------------------------------
// centroids: compact-then-accumulate. Block = (chunk, label, image).
// ---------------------------------------------------------------------------
#define CCHUNK 2
#define CROWS 545          // ceil(1089/2)
__global__ void centroid_kernel() {
    __shared__ int slist[CROWS];
    __shared__ int scnt;
    int ch = blockIdx.x, l = blockIdx.y, b = blockIdx.z;
    int t = threadIdx.x;
    int r0 = ch * CROWS;
    int r1 = (r0 + CROWS < HW) ? r0 + CROWS : HW;
    if (t == 0) scnt = 0;
    __syncthreads();
    for (int n = r0 + t; n < r1; n += 512) {
        if (g_labels[b * HW + n] == l) slist[atomicAdd(&scnt, 1)] = n;
    }
    __syncthreads();
    int cnt = scnt;
    if (cnt == 0) return;
    const __half* fb = g_h + (size_t)b * HW * DIM;
    float acc = 0.f;
    int i = 0;
    for (; i + 4 <= cnt; i += 4) {
        float v0 = __half2float(fb[(size_t)slist[i + 0] * DIM + t]);
        float v1 = __half2float(fb[(size_t)slist[i + 1] * DIM + t]);
        float v2 = __half2float(fb[(size_t)slist[i + 2] * DIM + t]);
        float v3 = __half2float(fb[(size_t)slist[i + 3] * DIM + t]);
        acc += (v0 + v1) + (v2 + v3);
    }
    for (; i < cnt; i++)
        acc += __half2float(fb[(size_t)slist[i] * DIM + t]);
    atomicAdd(&g_label_sums[b][l][t], acc);
    if (t == 0) atomicAdd(&g_cnt[b][l], (float)cnt);
}

// ---------------------------------------------------------------------------
// supcon Gram tile via mma.sync fp16. S-ONLY epilogue: P and C are derived
// analytically in rowpd from centroid sums (P_i = (e_i.lsum_l - cnt_l)/T,
// C_i = cnt_l - 1), so no label compares / P/C reductions here.
// Diagonal tiles reuse the A buffer for B (half the loads).
// ---------------------------------------------------------------------------
__global__ __launch_bounds__(512, 2) void supcon_mma_kernel() {
    extern __shared__ char smem[];
    uint32_t sb = smem_u32(smem);
    int tid = threadIdx.x;
    int wid = tid >> 5, lane = tid & 31;
    int wr = wid >> 2, wc = wid & 3;            // 4x4 warp grid, 32x32 tiles
    int b = blockIdx.y;
    int idx = blockIdx.x, rt = 0;
    while (idx >= CTILES - rt) { idx -= CTILES - rt; rt++; }
    int ct = rt + idx;
    bool diag = (ct == rt);
    int row0 = rt * 128, col0 = ct * 128;

    float* rowS = (float*)(smem + SM_ROWS);
    float* colS = (float*)(smem + SM_COLS);
    if (tid < 128) { rowS[tid] = 0.f; colS[tid] = 0.f; }

    const __half* bp = g_h + (size_t)b * HW * DIM;
    uint32_t boff = diag ? 0u : (uint32_t)MATSZ;   // diag: B == A buffer

    // ---- cp.async stage loader: A (+B if !diag), 128B rows, xor swizzle ----
    auto load_stage = [&](int c, int buf) {
        uint32_t dst_base = sb + SM_BUF + buf * STAGESZ;
#pragma unroll
        for (int it = 0; it < 4; it++) {
            int mat = it >> 1;                   // 0 = A, 1 = B
            if (mat == 1 && diag) break;
            int idxm = tid + 512 * (it & 1);     // 0..1023
            int row = idxm >> 3, seg = idxm & 7;
            int grow = ((mat == 0) ? row0 : col0) + row;
            uint32_t sz = (grow < HW) ? 16u : 0u;
            int gcl = (grow < HW) ? grow : 0;
            const __half* src = bp + (size_t)gcl * DIM + c * 64 + seg * 8;
            uint32_t dst = dst_base + mat * MATSZ + row * 128 +
                           (((uint32_t)(seg * 16)) ^ (((uint32_t)row & 7u) << 4));
            asm volatile("cp.async.cg.shared.global [%0], [%1], 16, %2;"
                         :: "r"(dst), "l"(src), "r"(sz) : "memory");
        }
        asm volatile("cp.async.commit_group;" ::: "memory");
    };

    // fragment address components (128B rows, swizzle mask (row&7)<<4)
    int a_r = wr * 32 + (lane & 15);
    uint32_t a_xm = (((uint32_t)lane) & 7u) << 4;
    uint32_t a_kb = (uint32_t)((lane >> 4) * 16);
    int b_n = wc * 32 + ((lane >> 4) & 1) * 8 + (lane & 7);
    uint32_t b_xm = (((uint32_t)lane) & 7u) << 4;
    uint32_t b_kb = (uint32_t)(((lane >> 3) & 1) * 16);

    float acc[2][4][4];
#pragma unroll
    for (int mt = 0; mt < 2; mt++)
#pragma unroll
        for (int nt = 0; nt < 4; nt++)
#pragma unroll
            for (int e = 0; e < 4; e++) acc[mt][nt][e] = 0.f;

    load_stage(0, 0);
    load_stage(1, 1);
    for (int c = 0; c < 8; c++) {
        if (c < 7) asm volatile("cp.async.wait_group 1;" ::: "memory");
        else       asm volatile("cp.async.wait_group 0;" ::: "memory");
        __syncthreads();   // chunk c visible; all warps done with c-1's buffer
        if (c + 2 < 8) load_stage(c + 2, (c + 2) % NSTAGE);
        uint32_t stg = sb + SM_BUF + (c % NSTAGE) * STAGESZ;
#pragma unroll
        for (int ks = 0; ks < 4; ks++) {
            uint32_t ka = (((uint32_t)(ks * 32)) + a_kb) ^ a_xm;
            uint32_t ah[2][4];
#pragma unroll
            for (int mt = 0; mt < 2; mt++) {
                uint32_t ad = stg + (uint32_t)((a_r + mt * 16) * 128) + ka;
                ldsm4(ah[mt], ad);
            }
            uint32_t kb2 = (((uint32_t)(ks * 32)) + b_kb) ^ b_xm;
#pragma unroll
            for (int ntp = 0; ntp < 2; ntp++) {
                uint32_t bh4[4];
                uint32_t bd = stg + boff + (uint32_t)((b_n + ntp * 16) * 128) + kb2;
                ldsm4(bh4, bd);
#pragma unroll
                for (int mt = 0; mt < 2; mt++) {
                    mma_f16(acc[mt][2 * ntp],     ah[mt], &bh4[0]);
                    mma_f16(acc[mt][2 * ntp + 1], ah[mt], &bh4[2]);
                }
            }
        }
    }
    __syncthreads();

    // ---- S-only epilogue: rows via shfl(1,2); cols per-nt via shfl(4,8,16) ----
    int lr4 = lane >> 2;
    float S[4];
    int rloc[4];
#pragma unroll
    for (int q = 0; q < 4; q++) {
        rloc[q] = wr * 32 + (q >> 1) * 16 + (q & 1) * 8 + lr4;
        S[q] = 0.f;
    }
#pragma unroll
    for (int nt = 0; nt < 4; nt++) {
        int cl0 = wc * 32 + nt * 8 + (lane & 3) * 2;
        int cg0 = col0 + cl0, cg1 = cg0 + 1;
        bool v0 = cg0 < HW, v1 = cg1 < HW;
        float Sc0 = 0.f, Sc1 = 0.f;
#pragma unroll
        for (int mt = 0; mt < 2; mt++)
#pragma unroll
            for (int h = 0; h < 2; h++) {
                int q = mt * 2 + h;
                int rg = row0 + rloc[q];
                float e0 = fexp((acc[mt][nt][h * 2 + 0] - 1.0f) * INV_T);
                float e1 = fexp((acc[mt][nt][h * 2 + 1] - 1.0f) * INV_T);
                if (rg < HW && v0 && cg0 != rg) { S[q] += e0; Sc0 += e0; }
                if (rg < HW && v1 && cg1 != rg) { S[q] += e1; Sc1 += e1; }
            }
        if (!diag) {
#pragma unroll
            for (int o = 4; o <= 16; o <<= 1) {
                Sc0 += __shfl_xor_sync(0xffffffffu, Sc0, o);
                Sc1 += __shfl_xor_sync(0xffffffffu, Sc1, o);
            }
            if (lane < 4) {
                atomicAdd(&colS[cl0], Sc0);
                atomicAdd(&colS[cl0 + 1], Sc1);
            }
        }
    }
#pragma unroll
    for (int q = 0; q < 4; q++) {
#pragma unroll
        for (int o = 1; o <= 2; o <<= 1)
            S[q] += __shfl_xor_sync(0xffffffffu, S[q], o);
    }
    if ((lane & 3) == 0) {
#pragma unroll
        for (int q = 0; q < 4; q++) atomicAdd(&rowS[rloc[q]], S[q]);
    }
    __syncthreads();
    if (tid < 128) {
        int rg = row0 + tid;
        if (rg < HW) atomicAdd(&g_S[b * HW + rg], rowS[tid]);
    } else if (tid < 256 && !diag) {
        int j = tid - 128;
        int cg = col0 + j;
        if (cg < HW) atomicAdd(&g_S[b * HW + cg], colS[j]);
    }
}

// ---------------------------------------------------------------------------
// rowpd: blocks [0,16) per-row supcon loss with analytic P/C:
//   C_i = cnt[l_i]-1,  P_i = (e_i . lsum_{l_i} - cnt_{l_i}) * INV_T
// blocks [16,32): centroid pair-dots.
// ---------------------------------------------------------------------------
__global__ void rowpd_kernel() {
    int t = threadIdx.x;
    if (blockIdx.x < BATCH) {
        int b = blockIdx.x;
        __shared__ float lsum[NLBL][DIM];     // 14 KB
        __shared__ float scnt[NLBL];
        for (int i = t; i < NLBL * DIM; i += 512)
            ((float*)lsum)[i] = ((const float*)g_label_sums[b])[i];
        if (t < NLBL) scnt[t] = g_cnt[b][t];
        __syncthreads();
        int wid = t >> 5, lane = t & 31;
        float s = 0.f, n = 0.f;
        for (int r = wid; r < HW; r += 16) {
            int l = g_labels[b * HW + r];
            float cl = scnt[l];
            if (cl >= 2.f) {
                const __half* er = g_h + ((size_t)b * HW + r) * DIM;
                uint4 u0 = ((const uint4*)er)[lane * 2];
                uint4 u1 = ((const uint4*)er)[lane * 2 + 1];
                __half hh[16];
                *(uint4*)hh = u0; *((uint4*)hh + 1) = u1;
                const float4* ls4 = (const float4*)(&lsum[l][lane * 16]);
                float4 a0 = ls4[0], a1 = ls4[1], a2 = ls4[2], a3 = ls4[3];
                float lsv[16] = {a0.x,a0.y,a0.z,a0.w, a1.x,a1.y,a1.z,a1.w,
                                 a2.x,a2.y,a2.z,a2.w, a3.x,a3.y,a3.z,a3.w};
                float dot = 0.f;
#pragma unroll
                for (int k = 0; k < 16; k++)
                    dot = fmaf(__half2float(hh[k]), lsv[k], dot);
#pragma unroll
                for (int o = 16; o > 0; o >>= 1)
                    dot += __shfl_xor_sync(0xffffffffu, dot, o);
                if (lane == 0) {
                    float C = cl - 1.f;
                    float P = (dot - cl) * INV_T;
                    s += -(P - C * logf(g_S[b * HW + r] + 1e-6f)) / C;
                    n += 1.f;
                }
            }
        }
        __shared__ float sS[16], sN[16];
        if (lane == 0) { sS[wid] = s; sN[wid] = n; }
        __syncthreads();
        if (t == 0) {
            float a = 0.f, c = 0.f;
            for (int i = 0; i < 16; i++) { a += sS[i]; c += sN[i]; }
            g_supcon_sum[b] = a; g_anchor_cnt[b] = c;
        }
    } else {
        int b = blockIdx.x - BATCH;
        int lane = t & 31;
        float inv[NLBL];
#pragma unroll
        for (int l = 0; l < NLBL; l++) inv[l] = 1.f / fmaxf(g_cnt[b][l], 1.f);
        float raw[NLBL], m[NLBL];
        float sall = 0.f;
#pragma unroll
        for (int l = 0; l < NLBL; l++) {
            raw[l] = g_label_sums[b][l][t];
            m[l] = raw[l] * inv[l];
            sall += raw[l];
        }
        sall *= (1.f / (float)HW);
        float part[NPD];
        int k = 0;
#pragma unroll
        for (int l1 = 0; l1 < NLBL; l1++)
#pragma unroll
            for (int l2 = l1; l2 < NLBL; l2++) part[k++] = m[l1] * m[l2];
        part[28] = sall * sall;
#pragma unroll
        for (int i = 0; i < NPD; i++)
#pragma unroll
            for (int o = 16; o > 0; o >>= 1) part[i] += __shfl_xor_sync(0xffffffffu, part[i], o);
        __shared__ float acc[NPD];
        if (t < NPD) acc[t] = 0.f;
        __syncthreads();
        if (lane == 0) {
#pragma unroll
            for (int i = 0; i < NPD; i++) atomicAdd(&acc[i], part[i]);
        }
        __syncthreads();
        if (t < NPD) g_pd[b][t] = acc[t];
    }
}

// ---------------------------------------------------------------------------
// finalize: pure scalar math. rn2 == 1 => var_l = 1 - ||mean_l||^2 etc.
// ---------------------------------------------------------------------------
__global__ void finalize_kernel(const float* __restrict__ is_forged, float* __restrict__ out) {
    __shared__ float sc[BATCH], scv[BATCH], sp[BATCH], spv[BATCH], un[BATCH], unv[BATCH];
    int t = threadIdx.x;
    if (t < BATCH) {
        int b = t;
        float na = g_anchor_cnt[b];
        float supcon = g_supcon_sum[b] / fmaxf(na, 1.f);
        float supcon_valid = (na > 0.f) ? 1.f : 0.f;

        float pd[NPD];
#pragma unroll
        for (int i = 0; i < NPD; i++) pd[i] = g_pd[b][i];
        float cnt[NLBL], cn[NLBL];
#pragma unroll
        for (int l = 0; l < NLBL; l++) {
            cnt[l] = g_cnt[b][l];
            cn[l] = pd[PD(l, l)];
        }
        float terms = 0.f, npairs = 0.f;
        int npresent = 0;
#pragma unroll
        for (int l = 0; l < NLBL; l++) if (cnt[l] > 0.f) npresent++;
#pragma unroll
        for (int l1 = 0; l1 < NLBL; l1++)
#pragma unroll
            for (int l2 = l1 + 1; l2 < NLBL; l2++) {
                if (cnt[l1] > 0.f && cnt[l2] > 0.f) {
                    float sq = cn[l1] + cn[l2] - 2.f * pd[PD(l1, l2)];
                    float dd = sqrtf(fmaxf(sq, 0.f));
                    terms += fmaxf(SEPM - dd, 0.f);
                    npairs += 1.f;
                }
            }
        float sep = terms / fmaxf(npairs, 1.f);
        float sep_valid = (npresent >= 2) ? 1.f : 0.f;

        float uni, univ;
        if (is_forged[b] >= 0.5f) {
            float inst = 0.f, nl = 0.f;
#pragma unroll
            for (int l = 0; l < NLBL; l++) {
                float var = 1.0f - cn[l];      // q_l/cnt_l == 1 (unit-norm rows)
                if (cnt[l] >= 2.f && var > UNITH) { inst += var - UNITH; nl += 1.f; }
            }
            uni = inst / fmaxf(nl, 1.f);
            univ = (nl > 0.f) ? 1.f : 0.f;
        } else {
            float var_all = 1.0f - pd[28];     // q_all/HW == 1
            uni = (var_all > UNITH) ? (var_all - UNITH) : 0.f;
            univ = (var_all > UNITH) ? 1.f : 0.f;
        }

        sc[b] = supcon * supcon_valid; scv[b] = supcon_valid;
        sp[b] = sep * sep_valid;       spv[b] = sep_valid;
        un[b] = uni * univ;            unv[b] = univ;
    }
    __syncthreads();
    if (t == 0) {
        float a = 0.f, av = 0.f, s2 = 0.f, sv = 0.f, u = 0.f, uv = 0.f;
        for (int b = 0; b < BATCH; b++) {
            a += sc[b]; av += scv[b];
            s2 += sp[b]; sv += spv[b];
            u += un[b]; uv += unv[b];
        }
        float supcon = (av > 0.f) ? a / fmaxf(av, 1.f) : 0.f;
        float sep = (sv > 0.f) ? s2 / fmaxf(sv, 1.f) : 0.f;
        float uni = (uv > 0.f) ? u / fmaxf(uv, 1.f) : 0.f;
        out[0] = 1.0f * supcon + 0.5f * sep + 0.5f * uni;
    }
}

// ---------------------------------------------------------------------------
extern "C" void kernel_launch(void* const* d_in, const int* in_sizes, int n_in,
                              void* d_out, int out_size) {
    const float* emb   = (const float*)d_in[0];   // (16,33,33,512) f32
    const float* masks = (const float*)d_in[1];   // (16,6,33,33) f32
    const float* isf   = (const float*)d_in[2];   // (16,) f32
    float* out = (float*)d_out;

    cudaFuncSetAttribute(supcon_mma_kernel,
                         cudaFuncAttributeMaxDynamicSharedMemorySize, SM_TOTAL);

    prepcvt_kernel<<<PBLK + CVTBLK, 256>>>(masks, emb);                // 0
    labels_kernel<<<(BATCH * HW + 255) / 256, 256>>>(masks);           // 1
    centroid_kernel<<<dim3(CCHUNK, NLBL, BATCH), 512>>>();             // 2
    supcon_mma_kernel<<<dim3(NTILEPAIRS, BATCH), 512, SM_TOTAL>>>();   // 3 (ncu slot)
    rowpd_kernel<<<2 * BATCH, 512>>>();                                // 4
    finalize_kernel<<<1, 32>>>(isf, out);                              // 5
}

// round 15
// speedup vs baseline: 1.4790x; 1.4790x over previous
#include <cuda_runtime.h>
#include <cuda_fp16.h>
#include <cstdint>
#include <math.h>

#define BATCH 16
#define NMASK 6
#define HW 1089
#define DIM 512
#define NLBL 7
#define INV_T (1.0f/0.07f)
#define SEPM 2.0f
#define UNITH 0.1f

#define CTILES 9          // ceil(1089/128)
#define NTILEPAIRS 45     // CTILES*(CTILES+1)/2
#define NPD 29            // 28 pair-dots + ||mean_all||^2

// ---- smem layout for supcon_mma (dynamic) ----
#define SM_ROWS 0                 // 128 floats (row S accum)
#define SM_COLS 512               // 128 floats (col S accum)
#define SM_BUF  1024
#define MATSZ   16384             // 128 rows x 64 fp16 (128B/row)
#define STAGESZ (2*MATSZ)         // A,B = 32KB
#define NSTAGE  3
#define SM_TOTAL (SM_BUF + NSTAGE*STAGESZ)   // 99328 -> 2 CTAs/SM

// ---- scratch (device globals: allocation-free) ----
__device__ float g_label_sums[BATCH][NLBL][DIM];
__device__ float g_cnt[BATCH][NLBL];
__device__ float g_supcon_sum[BATCH];
__device__ float g_anchor_cnt[BATCH];
__device__ float g_pd[BATCH][NPD];
__device__ int   g_active[BATCH * NMASK];
__device__ int   g_labels[BATCH * HW];
__device__ float g_S[BATCH * HW];
__device__ __align__(16) __half g_h[(size_t)BATCH * HW * DIM];

// ================= helpers =================
__device__ __forceinline__ uint32_t smem_u32(const void* p) {
    uint32_t a;
    asm("{ .reg .u64 t; cvta.to.shared.u64 t, %1; cvt.u32.u64 %0, t; }" : "=r"(a) : "l"(p));
    return a;
}
__device__ __forceinline__ void ldsm4(uint32_t* r, uint32_t addr) {
    asm volatile("ldmatrix.sync.aligned.m8n8.x4.shared.b16 {%0,%1,%2,%3}, [%4];"
                 : "=r"(r[0]), "=r"(r[1]), "=r"(r[2]), "=r"(r[3]) : "r"(addr));
}
__device__ __forceinline__ void mma_f16(float* c, const uint32_t* a, const uint32_t* b) {
    asm volatile("mma.sync.aligned.m16n8k16.row.col.f32.f16.f16.f32 "
                 "{%0,%1,%2,%3}, {%4,%5,%6,%7}, {%8,%9}, {%0,%1,%2,%3};"
                 : "+f"(c[0]), "+f"(c[1]), "+f"(c[2]), "+f"(c[3])
                 : "r"(a[0]), "r"(a[1]), "r"(a[2]), "r"(a[3]), "r"(b[0]), "r"(b[1]));
}
__device__ __forceinline__ int PD(int a, int c) { return a * 7 - (a * (a + 1)) / 2 + c; }

// Fast exp on FMA/ALU pipes (no MUFU): mean-one-tuned Schraudolph.
__device__ __forceinline__ float fexp(float x) {
    return __int_as_float((int)(fmaf(x, 12102203.0f, 1064870693.0f)));
}

// ---------------------------------------------------------------------------
// fused prep + zero + cvt:
//   blocks [0,96): mask-channel active flags
//   blocks [96,320): zero accumulators
//   blocks [320,4676): streaming fp32 -> fp16 conversion (rn2 == 1 exactly)
// ---------------------------------------------------------------------------
#define ZBLK 224
#define PBLK (BATCH * NMASK + ZBLK)               // 320
#define CVTBLK ((BATCH * HW * DIM) / (256 * 8))   // 4356
__global__ void prepcvt_kernel(const float* __restrict__ masks,
                               const float* __restrict__ emb) {
    int blk = blockIdx.x;
    if (blk < BATCH * NMASK) {
        const float* m = masks + (size_t)blk * HW;
        float s = 0.f;
        for (int i = threadIdx.x; i < HW; i += blockDim.x) s += m[i];
        __shared__ float sh[256];
        sh[threadIdx.x] = s;
        __syncthreads();
        for (int o = 128; o > 0; o >>= 1) {
            if (threadIdx.x < o) sh[threadIdx.x] += sh[threadIdx.x + o];
            __syncthreads();
        }
        if (threadIdx.x == 0) g_active[blk] = (sh[0] > 0.f) ? 1 : 0;
    } else if (blk < PBLK) {
        int i = (blk - BATCH * NMASK) * 256 + threadIdx.x;
        if (i < BATCH * HW) g_S[i] = 0.f;
        if (i < BATCH * NLBL * DIM) ((float*)g_label_sums)[i] = 0.f;
        if (i < BATCH * NLBL) ((float*)g_cnt)[i] = 0.f;
        if (i < BATCH) { g_supcon_sum[i] = 0.f; g_anchor_cnt[i] = 0.f; }
    } else {
        size_t i = ((size_t)(blk - PBLK) * 256 + threadIdx.x) * 8;
        float4 v0 = *(const float4*)(emb + i);
        float4 v1 = *(const float4*)(emb + i + 4);
        __half hh[8];
        hh[0] = __float2half(v0.x); hh[1] = __float2half(v0.y);
        hh[2] = __float2half(v0.z); hh[3] = __float2half(v0.w);
        hh[4] = __float2half(v1.x); hh[5] = __float2half(v1.y);
        hh[6] = __float2half(v1.z); hh[7] = __float2half(v1.w);
        *(uint4*)(g_h + i) = *(uint4*)hh;
    }
}

// ---------------------------------------------------------------------------
// labels
// ---------------------------------------------------------------------------
__global__ void labels_kernel(const float* __restrict__ masks) {
    int idx = blockIdx.x * blockDim.x + threadIdx.x;
    if (idx >= BATCH * HW) return;
    int b = idx / HW, n = idx - b * HW;
    const float* mb = masks + (size_t)b * NMASK * HW;
    int lbl = 0;
#pragma unroll
    for (int m = 0; m < NMASK; m++) {
        if (mb[(size_t)m * HW + n] > 0.5f && g_active[b * NMASK + m]) lbl = m + 1;
    }
    g_labels[idx] = lbl;
}

// ---------------------------------------------------------------------------
// centroids: compact-then-accumulate. Block = (chunk, label, image).
// ---------------------------------------------------------------------------
#define CCHUNK 2
#define CROWS 545          // ceil(1089/2)
__global__ void centroid_kernel() {
    __shared__ int slist[CROWS];
    __shared__ int scnt;
    int ch = blockIdx.x, l = blockIdx.y, b = blockIdx.z;
    int t = threadIdx.x;
    int r0 = ch * CROWS;
    int r1 = (r0 + CROWS < HW) ? r0 + CROWS : HW;
    if (t == 0) scnt = 0;
    __syncthreads();
    for (int n = r0 + t; n < r1; n += 512) {
        if (g_labels[b * HW + n] == l) slist[atomicAdd(&scnt, 1)] = n;
    }
    __syncthreads();
    int cnt = scnt;
    if (cnt == 0) return;
    const __half* fb = g_h + (size_t)b * HW * DIM;
    float acc = 0.f;
    int i = 0;
    for (; i + 4 <= cnt; i += 4) {
        float v0 = __half2float(fb[(size_t)slist[i + 0] * DIM + t]);
        float v1 = __half2float(fb[(size_t)slist[i + 1] * DIM + t]);
        float v2 = __half2float(fb[(size_t)slist[i + 2] * DIM + t]);
        float v3 = __half2float(fb[(size_t)slist[i + 3] * DIM + t]);
        acc += (v0 + v1) + (v2 + v3);
    }
    for (; i < cnt; i++)
        acc += __half2float(fb[(size_t)slist[i] * DIM + t]);
    atomicAdd(&g_label_sums[b][l][t], acc);
    if (t == 0) atomicAdd(&g_cnt[b][l], (float)cnt);
}

// ---------------------------------------------------------------------------
// supcon Gram tile via mma.sync fp16. S-ONLY epilogue (P/C analytic in
// rowloss). Diagonal tiles reuse the A buffer for B (half the loads).
// ---------------------------------------------------------------------------
__global__ __launch_bounds__(512, 2) void supcon_mma_kernel() {
    extern __shared__ char smem[];
    uint32_t sb = smem_u32(smem);
    int tid = threadIdx.x;
    int wid = tid >> 5, lane = tid & 31;
    int wr = wid >> 2, wc = wid & 3;            // 4x4 warp grid, 32x32 tiles
    int b = blockIdx.y;
    int idx = blockIdx.x, rt = 0;
    while (idx >= CTILES - rt) { idx -= CTILES - rt; rt++; }
    int ct = rt + idx;
    bool diag = (ct == rt);
    int row0 = rt * 128, col0 = ct * 128;

    float* rowS = (float*)(smem + SM_ROWS);
    float* colS = (float*)(smem + SM_COLS);
    if (tid < 128) { rowS[tid] = 0.f; colS[tid] = 0.f; }

    const __half* bp = g_h + (size_t)b * HW * DIM;
    uint32_t boff = diag ? 0u : (uint32_t)MATSZ;   // diag: B == A buffer

    // ---- cp.async stage loader: A (+B if !diag), 128B rows, xor swizzle ----
    auto load_stage = [&](int c, int buf) {
        uint32_t dst_base = sb + SM_BUF + buf * STAGESZ;
#pragma unroll
        for (int it = 0; it < 4; it++) {
            int mat = it >> 1;                   // 0 = A, 1 = B
            if (mat == 1 && diag) break;
            int idxm = tid + 512 * (it & 1);     // 0..1023
            int row = idxm >> 3, seg = idxm & 7;
            int grow = ((mat == 0) ? row0 : col0) + row;
            uint32_t sz = (grow < HW) ? 16u : 0u;
            int gcl = (grow < HW) ? grow : 0;
            const __half* src = bp + (size_t)gcl * DIM + c * 64 + seg * 8;
            uint32_t dst = dst_base + mat * MATSZ + row * 128 +
                           (((uint32_t)(seg * 16)) ^ (((uint32_t)row & 7u) << 4));
            asm volatile("cp.async.cg.shared.global [%0], [%1], 16, %2;"
                         :: "r"(dst), "l"(src), "r"(sz) : "memory");
        }
        asm volatile("cp.async.commit_group;" ::: "memory");
    };

    // fragment address components (128B rows, swizzle mask (row&7)<<4)
    int a_r = wr * 32 + (lane & 15);
    uint32_t a_xm = (((uint32_t)lane) & 7u) << 4;
    uint32_t a_kb = (uint32_t)((lane >> 4) * 16);
    int b_n = wc * 32 + ((lane >> 4) & 1) * 8 + (lane & 7);
    uint32_t b_xm = (((uint32_t)lane) & 7u) << 4;
    uint32_t b_kb = (uint32_t)(((lane >> 3) & 1) * 16);

    float acc[2][4][4];
#pragma unroll
    for (int mt = 0; mt < 2; mt++)
#pragma unroll
        for (int nt = 0; nt < 4; nt++)
#pragma unroll
            for (int e = 0; e < 4; e++) acc[mt][nt][e] = 0.f;

    load_stage(0, 0);
    load_stage(1, 1);
    for (int c = 0; c < 8; c++) {
        if (c < 7) asm volatile("cp.async.wait_group 1;" ::: "memory");
        else       asm volatile("cp.async.wait_group 0;" ::: "memory");
        __syncthreads();   // chunk c visible; all warps done with c-1's buffer
        if (c + 2 < 8) load_stage(c + 2, (c + 2) % NSTAGE);
        uint32_t stg = sb + SM_BUF + (c % NSTAGE) * STAGESZ;
#pragma unroll
        for (int ks = 0; ks < 4; ks++) {
            uint32_t ka = (((uint32_t)(ks * 32)) + a_kb) ^ a_xm;
            uint32_t ah[2][4];
#pragma unroll
            for (int mt = 0; mt < 2; mt++) {
                uint32_t ad = stg + (uint32_t)((a_r + mt * 16) * 128) + ka;
                ldsm4(ah[mt], ad);
            }
            uint32_t kb2 = (((uint32_t)(ks * 32)) + b_kb) ^ b_xm;
#pragma unroll
            for (int ntp = 0; ntp < 2; ntp++) {
                uint32_t bh4[4];
                uint32_t bd = stg + boff + (uint32_t)((b_n + ntp * 16) * 128) + kb2;
                ldsm4(bh4, bd);
#pragma unroll
                for (int mt = 0; mt < 2; mt++) {
                    mma_f16(acc[mt][2 * ntp],     ah[mt], &bh4[0]);
                    mma_f16(acc[mt][2 * ntp + 1], ah[mt], &bh4[2]);
                }
            }
        }
    }
    __syncthreads();

    // ---- S-only epilogue: rows via shfl(1,2); cols per-nt via shfl(4,8,16) ----
    int lr4 = lane >> 2;
    float S[4];
    int rloc[4];
#pragma unroll
    for (int q = 0; q < 4; q++) {
        rloc[q] = wr * 32 + (q >> 1) * 16 + (q & 1) * 8 + lr4;
        S[q] = 0.f;
    }
#pragma unroll
    for (int nt = 0; nt < 4; nt++) {
        int cl0 = wc * 32 + nt * 8 + (lane & 3) * 2;
        int cg0 = col0 + cl0, cg1 = cg0 + 1;
        bool v0 = cg0 < HW, v1 = cg1 < HW;
        float Sc0 = 0.f, Sc1 = 0.f;
#pragma unroll
        for (int mt = 0; mt < 2; mt++)
#pragma unroll
            for (int h = 0; h < 2; h++) {
                int q = mt * 2 + h;
                int rg = row0 + rloc[q];
                float e0 = fexp((acc[mt][nt][h * 2 + 0] - 1.0f) * INV_T);
                float e1 = fexp((acc[mt][nt][h * 2 + 1] - 1.0f) * INV_T);
                if (rg < HW && v0 && cg0 != rg) { S[q] += e0; Sc0 += e0; }
                if (rg < HW && v1 && cg1 != rg) { S[q] += e1; Sc1 += e1; }
            }
        if (!diag) {
#pragma unroll
            for (int o = 4; o <= 16; o <<= 1) {
                Sc0 += __shfl_xor_sync(0xffffffffu, Sc0, o);
                Sc1 += __shfl_xor_sync(0xffffffffu, Sc1, o);
            }
            if (lane < 4) {
                atomicAdd(&colS[cl0], Sc0);
                atomicAdd(&colS[cl0 + 1], Sc1);
            }
        }
    }
#pragma unroll
    for (int q = 0; q < 4; q++) {
#pragma unroll
        for (int o = 1; o <= 2; o <<= 1)
            S[q] += __shfl_xor_sync(0xffffffffu, S[q], o);
    }
    if ((lane & 3) == 0) {
#pragma unroll
        for (int q = 0; q < 4; q++) atomicAdd(&rowS[rloc[q]], S[q]);
    }
    __syncthreads();
    if (tid < 128) {
        int rg = row0 + tid;
        if (rg < HW) atomicAdd(&g_S[b * HW + rg], rowS[tid]);
    } else if (tid < 256 && !diag) {
        int j = tid - 128;
        int cg = col0 + j;
        if (cg < HW) atomicAdd(&g_S[b * HW + cg], colS[j]);
    }
}

// ---------------------------------------------------------------------------
// rowloss: one warp per row (full-chip parallel). Analytic P/C:
//   C_i = cnt[l]-1,  P_i = (e_i . lsum_l - cnt_l) * INV_T
// lane 0 atomically accumulates per-image loss and anchor count.
// ---------------------------------------------------------------------------
#define RLBLK ((BATCH * HW) / 8)   // 2178 blocks x 8 warps = 17424 rows
__global__ void rowloss_kernel() {
    int w = blockIdx.x * 8 + (threadIdx.x >> 5);
    int lane = threadIdx.x & 31;
    int b = w / HW;
    int l = g_labels[w];
    float cl = g_cnt[b][l];
    if (cl < 2.f) return;
    const __half* er = g_h + (size_t)w * DIM;
    uint4 u0 = ((const uint4*)er)[lane * 2];
    uint4 u1 = ((const uint4*)er)[lane * 2 + 1];
    __half hh[16];
    *(uint4*)hh = u0; *((uint4*)hh + 1) = u1;
    const float4* ls4 = (const float4*)(&g_label_sums[b][l][lane * 16]);
    float4 a0 = ls4[0], a1 = ls4[1], a2 = ls4[2], a3 = ls4[3];
    float lsv[16] = {a0.x,a0.y,a0.z,a0.w, a1.x,a1.y,a1.z,a1.w,
                     a2.x,a2.y,a2.z,a2.w, a3.x,a3.y,a3.z,a3.w};
    float dot = 0.f;
#pragma unroll
    for (int k = 0; k < 16; k++)
        dot = fmaf(__half2float(hh[k]), lsv[k], dot);
#pragma unroll
    for (int o = 16; o > 0; o >>= 1)
        dot += __shfl_xor_sync(0xffffffffu, dot, o);
    if (lane == 0) {
        float C = cl - 1.f;
        float P = (dot - cl) * INV_T;
        float loss = -(P - C * logf(g_S[w] + 1e-6f)) / C;
        atomicAdd(&g_supcon_sum[b], loss);
        atomicAdd(&g_anchor_cnt[b], 1.f);
    }
}

// ---------------------------------------------------------------------------
// pd: per-image centroid pair-dots (16 blocks x 512, thread = dim)
// ---------------------------------------------------------------------------
__global__ void pd_kernel() {
    int b = blockIdx.x;
    int t = threadIdx.x;
    int lane = t & 31;
    float inv[NLBL];
#pragma unroll
    for (int l = 0; l < NLBL; l++) inv[l] = 1.f / fmaxf(g_cnt[b][l], 1.f);
    float raw[NLBL], m[NLBL];
    float sall = 0.f;
#pragma unroll
    for (int l = 0; l < NLBL; l++) {
        raw[l] = g_label_sums[b][l][t];
        m[l] = raw[l] * inv[l];
        sall += raw[l];
    }
    sall *= (1.f / (float)HW);
    float part[NPD];
    int k = 0;
#pragma unroll
    for (int l1 = 0; l1 < NLBL; l1++)
#pragma unroll
        for (int l2 = l1; l2 < NLBL; l2++) part[k++] = m[l1] * m[l2];
    part[28] = sall * sall;
#pragma unroll
    for (int i = 0; i < NPD; i++)
#pragma unroll
        for (int o = 16; o > 0; o >>= 1) part[i] += __shfl_xor_sync(0xffffffffu, part[i], o);
    __shared__ float acc[NPD];
    if (t < NPD) acc[t] = 0.f;
    __syncthreads();
    if (lane == 0) {
#pragma unroll
        for (int i = 0; i < NPD; i++) atomicAdd(&acc[i], part[i]);
    }
    __syncthreads();
    if (t < NPD) g_pd[b][t] = acc[t];
}

// ---------------------------------------------------------------------------
// finalize: pure scalar math. rn2 == 1 => var_l = 1 - ||mean_l||^2 etc.
// ---------------------------------------------------------------------------
__global__ void finalize_kernel(const float* __restrict__ is_forged, float* __restrict__ out) {
    __shared__ float sc[BATCH], scv[BATCH], sp[BATCH], spv[BATCH], un[BATCH], unv[BATCH];
    int t = threadIdx.x;
    if (t < BATCH) {
        int b = t;
        float na = g_anchor_cnt[b];
        float supcon = g_supcon_sum[b] / fmaxf(na, 1.f);
        float supcon_valid = (na > 0.f) ? 1.f : 0.f;

        float pd[NPD];
#pragma unroll
        for (int i = 0; i < NPD; i++) pd[i] = g_pd[b][i];
        float cnt[NLBL], cn[NLBL];
#pragma unroll
        for (int l = 0; l < NLBL; l++) {
            cnt[l] = g_cnt[b][l];
            cn[l] = pd[PD(l, l)];
        }
        float terms = 0.f, npairs = 0.f;
        int npresent = 0;
#pragma unroll
        for (int l = 0; l < NLBL; l++) if (cnt[l] > 0.f) npresent++;
#pragma unroll
        for (int l1 = 0; l1 < NLBL; l1++)
#pragma unroll
            for (int l2 = l1 + 1; l2 < NLBL; l2++) {
                if (cnt[l1] > 0.f && cnt[l2] > 0.f) {
                    float sq = cn[l1] + cn[l2] - 2.f * pd[PD(l1, l2)];
                    float dd = sqrtf(fmaxf(sq, 0.f));
                    terms += fmaxf(SEPM - dd, 0.f);
                    npairs += 1.f;
                }
            }
        float sep = terms / fmaxf(npairs, 1.f);
        float sep_valid = (npresent >= 2) ? 1.f : 0.f;

        float uni, univ;
        if (is_forged[b] >= 0.5f) {
            float inst = 0.f, nl = 0.f;
#pragma unroll
            for (int l = 0; l < NLBL; l++) {
                float var = 1.0f - cn[l];      // q_l/cnt_l == 1 (unit-norm rows)
                if (cnt[l] >= 2.f && var > UNITH) { inst += var - UNITH; nl += 1.f; }
            }
            uni = inst / fmaxf(nl, 1.f);
            univ = (nl > 0.f) ? 1.f : 0.f;
        } else {
            float var_all = 1.0f - pd[28];     // q_all/HW == 1
            uni = (var_all > UNITH) ? (var_all - UNITH) : 0.f;
            univ = (var_all > UNITH) ? 1.f : 0.f;
        }

        sc[b] = supcon * supcon_valid; scv[b] = supcon_valid;
        sp[b] = sep * sep_valid;       spv[b] = sep_valid;
        un[b] = uni * univ;            unv[b] = univ;
    }
    __syncthreads();
    if (t == 0) {
        float a = 0.f, av = 0.f, s2 = 0.f, sv = 0.f, u = 0.f, uv = 0.f;
        for (int b = 0; b < BATCH; b++) {
            a += sc[b]; av += scv[b];
            s2 += sp[b]; sv += spv[b];
            u += un[b]; uv += unv[b];
        }
        float supcon = (av > 0.f) ? a / fmaxf(av, 1.f) : 0.f;
        float sep = (sv > 0.f) ? s2 / fmaxf(sv, 1.f) : 0.f;
        float uni = (uv > 0.f) ? u / fmaxf(uv, 1.f) : 0.f;
        out[0] = 1.0f * supcon + 0.5f * sep + 0.5f * uni;
    }
}

// ---------------------------------------------------------------------------
extern "C" void kernel_launch(void* const* d_in, const int* in_sizes, int n_in,
                              void* d_out, int out_size) {
    const float* emb   = (const float*)d_in[0];   // (16,33,33,512) f32
    const float* masks = (const float*)d_in[1];   // (16,6,33,33) f32
    const float* isf   = (const float*)d_in[2];   // (16,) f32
    float* out = (float*)d_out;

    cudaFuncSetAttribute(supcon_mma_kernel,
                         cudaFuncAttributeMaxDynamicSharedMemorySize, SM_TOTAL);

    prepcvt_kernel<<<PBLK + CVTBLK, 256>>>(masks, emb);                // 0
    labels_kernel<<<(BATCH * HW + 255) / 256, 256>>>(masks);           // 1
    centroid_kernel<<<dim3(CCHUNK, NLBL, BATCH), 512>>>();             // 2
    supcon_mma_kernel<<<dim3(NTILEPAIRS, BATCH), 512, SM_TOTAL>>>();   // 3 (ncu slot)
    rowloss_kernel<<<RLBLK, 256>>>();                                  // 4
    pd_kernel<<<BATCH, 512>>>();                                       // 5
    finalize_kernel<<<1, 32>>>(isf, out);                              // 6
}

// round 16
// speedup vs baseline: 1.8160x; 1.2279x over previous
#include <cuda_runtime.h>
#include <cuda_fp16.h>
#include <cstdint>
#include <math.h>

#define BATCH 16
#define NMASK 6
#define HW 1089
#define DIM 512
#define NLBL 7
#define INV_T (1.0f/0.07f)
#define SEPM 2.0f
#define UNITH 0.1f

#define CTILES 9          // ceil(1089/128)
#define NTILEPAIRS 45     // CTILES*(CTILES+1)/2
#define NPD 29            // 28 pair-dots + ||mean_all||^2

// ---- smem layout for supcon_mma (dynamic) ----
#define SM_ROWS 0                 // 128 floats (row S accum)
#define SM_COLS 512               // 128 floats (col S accum)
#define SM_BUF  1024
#define MATSZ   16384             // 128 rows x 64 fp16 (128B/row)
#define STAGESZ (2*MATSZ)         // A,B = 32KB
#define NSTAGE  3
#define SM_TOTAL (SM_BUF + NSTAGE*STAGESZ)   // 99328 -> 2 CTAs/SM

// ---- scratch (device globals: allocation-free) ----
__device__ float g_label_sums[BATCH][NLBL][DIM];
__device__ float g_cnt[BATCH][NLBL];
__device__ float g_supcon_sum[BATCH];
__device__ float g_pd[BATCH][NPD];
__device__ int   g_active[BATCH * NMASK];
__device__ int   g_labels[BATCH * HW];
__device__ float g_S[BATCH * HW];
__device__ __align__(16) __half g_h[(size_t)BATCH * HW * DIM];

// ================= helpers =================
__device__ __forceinline__ uint32_t smem_u32(const void* p) {
    uint32_t a;
    asm("{ .reg .u64 t; cvta.to.shared.u64 t, %1; cvt.u32.u64 %0, t; }" : "=r"(a) : "l"(p));
    return a;
}
__device__ __forceinline__ void ldsm4(uint32_t* r, uint32_t addr) {
    asm volatile("ldmatrix.sync.aligned.m8n8.x4.shared.b16 {%0,%1,%2,%3}, [%4];"
                 : "=r"(r[0]), "=r"(r[1]), "=r"(r[2]), "=r"(r[3]) : "r"(addr));
}
__device__ __forceinline__ void mma_f16(float* c, const uint32_t* a, const uint32_t* b) {
    asm volatile("mma.sync.aligned.m16n8k16.row.col.f32.f16.f16.f32 "
                 "{%0,%1,%2,%3}, {%4,%5,%6,%7}, {%8,%9}, {%0,%1,%2,%3};"
                 : "+f"(c[0]), "+f"(c[1]), "+f"(c[2]), "+f"(c[3])
                 : "r"(a[0]), "r"(a[1]), "r"(a[2]), "r"(a[3]), "r"(b[0]), "r"(b[1]));
}
__device__ __forceinline__ int PD(int a, int c) { return a * 7 - (a * (a + 1)) / 2 + c; }

// Fast exp on FMA/ALU pipes (no MUFU): mean-one-tuned Schraudolph.
__device__ __forceinline__ float fexp(float x) {
    return __int_as_float((int)(fmaf(x, 12102203.0f, 1064870693.0f)));
}

// ---------------------------------------------------------------------------
// fused prep + zero + cvt:
//   blocks [0,96): mask-channel active flags
//   blocks [96,320): zero accumulators
//   blocks [320,4676): streaming fp32 -> fp16 conversion (rn2 == 1 exactly)
// ---------------------------------------------------------------------------
#define ZBLK 224
#define PBLK (BATCH * NMASK + ZBLK)               // 320
#define CVTBLK ((BATCH * HW * DIM) / (256 * 8))   // 4356
__global__ void prepcvt_kernel(const float* __restrict__ masks,
                               const float* __restrict__ emb) {
    int blk = blockIdx.x;
    if (blk < BATCH * NMASK) {
        const float* m = masks + (size_t)blk * HW;
        float s = 0.f;
        for (int i = threadIdx.x; i < HW; i += blockDim.x) s += m[i];
        __shared__ float sh[256];
        sh[threadIdx.x] = s;
        __syncthreads();
        for (int o = 128; o > 0; o >>= 1) {
            if (threadIdx.x < o) sh[threadIdx.x] += sh[threadIdx.x + o];
            __syncthreads();
        }
        if (threadIdx.x == 0) g_active[blk] = (sh[0] > 0.f) ? 1 : 0;
    } else if (blk < PBLK) {
        int i = (blk - BATCH * NMASK) * 256 + threadIdx.x;
        if (i < BATCH * HW) g_S[i] = 0.f;
        if (i < BATCH * NLBL * DIM) ((float*)g_label_sums)[i] = 0.f;
        if (i < BATCH * NLBL) ((float*)g_cnt)[i] = 0.f;
        if (i < BATCH) g_supcon_sum[i] = 0.f;
    } else {
        size_t i = ((size_t)(blk - PBLK) * 256 + threadIdx.x) * 8;
        float4 v0 = *(const float4*)(emb + i);
        float4 v1 = *(const float4*)(emb + i + 4);
        __half hh[8];
        hh[0] = __float2half(v0.x); hh[1] = __float2half(v0.y);
        hh[2] = __float2half(v0.z); hh[3] = __float2half(v0.w);
        hh[4] = __float2half(v1.x); hh[5] = __float2half(v1.y);
        hh[6] = __float2half(v1.z); hh[7] = __float2half(v1.w);
        *(uint4*)(g_h + i) = *(uint4*)hh;
    }
}

// ---------------------------------------------------------------------------
// labels
// ---------------------------------------------------------------------------
__global__ void labels_kernel(const float* __restrict__ masks) {
    int idx = blockIdx.x * blockDim.x + threadIdx.x;
    if (idx >= BATCH * HW) return;
    int b = idx / HW, n = idx - b * HW;
    const float* mb = masks + (size_t)b * NMASK * HW;
    int lbl = 0;
#pragma unroll
    for (int m = 0; m < NMASK; m++) {
        if (mb[(size_t)m * HW + n] > 0.5f && g_active[b * NMASK + m]) lbl = m + 1;
    }
    g_labels[idx] = lbl;
}

// ---------------------------------------------------------------------------
// centroids: compact-then-accumulate. Block = (chunk, label, image).
// ---------------------------------------------------------------------------
#define CCHUNK 2
#define CROWS 545          // ceil(1089/2)
__global__ void centroid_kernel() {
    __shared__ int slist[CROWS];
    __shared__ int scnt;
    int ch = blockIdx.x, l = blockIdx.y, b = blockIdx.z;
    int t = threadIdx.x;
    int r0 = ch * CROWS;
    int r1 = (r0 + CROWS < HW) ? r0 + CROWS : HW;
    if (t == 0) scnt = 0;
    __syncthreads();
    for (int n = r0 + t; n < r1; n += 512) {
        if (g_labels[b * HW + n] == l) slist[atomicAdd(&scnt, 1)] = n;
    }
    __syncthreads();
    int cnt = scnt;
    if (cnt == 0) return;
    const __half* fb = g_h + (size_t)b * HW * DIM;
    float acc = 0.f;
    int i = 0;
    for (; i + 4 <= cnt; i += 4) {
        float v0 = __half2float(fb[(size_t)slist[i + 0] * DIM + t]);
        float v1 = __half2float(fb[(size_t)slist[i + 1] * DIM + t]);
        float v2 = __half2float(fb[(size_t)slist[i + 2] * DIM + t]);
        float v3 = __half2float(fb[(size_t)slist[i + 3] * DIM + t]);
        acc += (v0 + v1) + (v2 + v3);
    }
    for (; i < cnt; i++)
        acc += __half2float(fb[(size_t)slist[i] * DIM + t]);
    atomicAdd(&g_label_sums[b][l][t], acc);
    if (t == 0) atomicAdd(&g_cnt[b][l], (float)cnt);
}

// ---------------------------------------------------------------------------
// supcon Gram tile via mma.sync fp16. S-ONLY epilogue (P/C analytic in
// rowloss). Diagonal tiles reuse the A buffer for B (half the loads).
// ---------------------------------------------------------------------------
__global__ __launch_bounds__(512, 2) void supcon_mma_kernel() {
    extern __shared__ char smem[];
    uint32_t sb = smem_u32(smem);
    int tid = threadIdx.x;
    int wid = tid >> 5, lane = tid & 31;
    int wr = wid >> 2, wc = wid & 3;            // 4x4 warp grid, 32x32 tiles
    int b = blockIdx.y;
    int idx = blockIdx.x, rt = 0;
    while (idx >= CTILES - rt) { idx -= CTILES - rt; rt++; }
    int ct = rt + idx;
    bool diag = (ct == rt);
    int row0 = rt * 128, col0 = ct * 128;

    float* rowS = (float*)(smem + SM_ROWS);
    float* colS = (float*)(smem + SM_COLS);
    if (tid < 128) { rowS[tid] = 0.f; colS[tid] = 0.f; }

    const __half* bp = g_h + (size_t)b * HW * DIM;
    uint32_t boff = diag ? 0u : (uint32_t)MATSZ;   // diag: B == A buffer

    // ---- cp.async stage loader: A (+B if !diag), 128B rows, xor swizzle ----
    auto load_stage = [&](int c, int buf) {
        uint32_t dst_base = sb + SM_BUF + buf * STAGESZ;
#pragma unroll
        for (int it = 0; it < 4; it++) {
            int mat = it >> 1;                   // 0 = A, 1 = B
            if (mat == 1 && diag) break;
            int idxm = tid + 512 * (it & 1);     // 0..1023
            int row = idxm >> 3, seg = idxm & 7;
            int grow = ((mat == 0) ? row0 : col0) + row;
            uint32_t sz = (grow < HW) ? 16u : 0u;
            int gcl = (grow < HW) ? grow : 0;
            const __half* src = bp + (size_t)gcl * DIM + c * 64 + seg * 8;
            uint32_t dst = dst_base + mat * MATSZ + row * 128 +
                           (((uint32_t)(seg * 16)) ^ (((uint32_t)row & 7u) << 4));
            asm volatile("cp.async.cg.shared.global [%0], [%1], 16, %2;"
                         :: "r"(dst), "l"(src), "r"(sz) : "memory");
        }
        asm volatile("cp.async.commit_group;" ::: "memory");
    };

    // fragment address components (128B rows, swizzle mask (row&7)<<4)
    int a_r = wr * 32 + (lane & 15);
    uint32_t a_xm = (((uint32_t)lane) & 7u) << 4;
    uint32_t a_kb = (uint32_t)((lane >> 4) * 16);
    int b_n = wc * 32 + ((lane >> 4) & 1) * 8 + (lane & 7);
    uint32_t b_xm = (((uint32_t)lane) & 7u) << 4;
    uint32_t b_kb = (uint32_t)(((lane >> 3) & 1) * 16);

    float acc[2][4][4];
#pragma unroll
    for (int mt = 0; mt < 2; mt++)
#pragma unroll
        for (int nt = 0; nt < 4; nt++)
#pragma unroll
            for (int e = 0; e < 4; e++) acc[mt][nt][e] = 0.f;

    load_stage(0, 0);
    load_stage(1, 1);
    for (int c = 0; c < 8; c++) {
        if (c < 7) asm volatile("cp.async.wait_group 1;" ::: "memory");
        else       asm volatile("cp.async.wait_group 0;" ::: "memory");
        __syncthreads();   // chunk c visible; all warps done with c-1's buffer
        if (c + 2 < 8) load_stage(c + 2, (c + 2) % NSTAGE);
        uint32_t stg = sb + SM_BUF + (c % NSTAGE) * STAGESZ;
#pragma unroll
        for (int ks = 0; ks < 4; ks++) {
            uint32_t ka = (((uint32_t)(ks * 32)) + a_kb) ^ a_xm;
            uint32_t ah[2][4];
#pragma unroll
            for (int mt = 0; mt < 2; mt++) {
                uint32_t ad = stg + (uint32_t)((a_r + mt * 16) * 128) + ka;
                ldsm4(ah[mt], ad);
            }
            uint32_t kb2 = (((uint32_t)(ks * 32)) + b_kb) ^ b_xm;
#pragma unroll
            for (int ntp = 0; ntp < 2; ntp++) {
                uint32_t bh4[4];
                uint32_t bd = stg + boff + (uint32_t)((b_n + ntp * 16) * 128) + kb2;
                ldsm4(bh4, bd);
#pragma unroll
                for (int mt = 0; mt < 2; mt++) {
                    mma_f16(acc[mt][2 * ntp],     ah[mt], &bh4[0]);
                    mma_f16(acc[mt][2 * ntp + 1], ah[mt], &bh4[2]);
                }
            }
        }
    }
    __syncthreads();

    // ---- S-only epilogue: rows via shfl(1,2); cols per-nt via shfl(4,8,16) ----
    int lr4 = lane >> 2;
    float S[4];
    int rloc[4];
#pragma unroll
    for (int q = 0; q < 4; q++) {
        rloc[q] = wr * 32 + (q >> 1) * 16 + (q & 1) * 8 + lr4;
        S[q] = 0.f;
    }
#pragma unroll
    for (int nt = 0; nt < 4; nt++) {
        int cl0 = wc * 32 + nt * 8 + (lane & 3) * 2;
        int cg0 = col0 + cl0, cg1 = cg0 + 1;
        bool v0 = cg0 < HW, v1 = cg1 < HW;
        float Sc0 = 0.f, Sc1 = 0.f;
#pragma unroll
        for (int mt = 0; mt < 2; mt++)
#pragma unroll
            for (int h = 0; h < 2; h++) {
                int q = mt * 2 + h;
                int rg = row0 + rloc[q];
                float e0 = fexp((acc[mt][nt][h * 2 + 0] - 1.0f) * INV_T);
                float e1 = fexp((acc[mt][nt][h * 2 + 1] - 1.0f) * INV_T);
                if (rg < HW && v0 && cg0 != rg) { S[q] += e0; Sc0 += e0; }
                if (rg < HW && v1 && cg1 != rg) { S[q] += e1; Sc1 += e1; }
            }
        if (!diag) {
#pragma unroll
            for (int o = 4; o <= 16; o <<= 1) {
                Sc0 += __shfl_xor_sync(0xffffffffu, Sc0, o);
                Sc1 += __shfl_xor_sync(0xffffffffu, Sc1, o);
            }
            if (lane < 4) {
                atomicAdd(&colS[cl0], Sc0);
                atomicAdd(&colS[cl0 + 1], Sc1);
            }
        }
    }
#pragma unroll
    for (int q = 0; q < 4; q++) {
#pragma unroll
        for (int o = 1; o <= 2; o <<= 1)
            S[q] += __shfl_xor_sync(0xffffffffu, S[q], o);
    }
    if ((lane & 3) == 0) {
#pragma unroll
        for (int q = 0; q < 4; q++) atomicAdd(&rowS[rloc[q]], S[q]);
    }
    __syncthreads();
    if (tid < 128) {
        int rg = row0 + tid;
        if (rg < HW) atomicAdd(&g_S[b * HW + rg], rowS[tid]);
    } else if (tid < 256 && !diag) {
        int j = tid - 128;
        int cg = col0 + j;
        if (cg < HW) atomicAdd(&g_S[b * HW + cg], colS[j]);
    }
}

// ---------------------------------------------------------------------------
// rowloss: one warp per row. Analytic P/C:
//   C_i = cnt[l]-1,  P_i = (e_i . lsum_l - cnt_l) * INV_T
// Block-level reduction (8 warps -> <=2 images) before the global atomic:
// total atomics ~2.9K instead of 35K (kills L2 atomic serialization).
// ---------------------------------------------------------------------------
#define RLBLK ((BATCH * HW) / 8)   // 2178 blocks x 8 warps = 17424 rows
__global__ void rowloss_kernel() {
    __shared__ float lv[8];
    __shared__ int bv[8];
    int wslot = threadIdx.x >> 5;
    int w = blockIdx.x * 8 + wslot;
    int lane = threadIdx.x & 31;
    int b = w / HW;
    int l = g_labels[w];
    float cl = g_cnt[b][l];
    float loss = 0.f;
    if (cl >= 2.f) {
        const __half* er = g_h + (size_t)w * DIM;
        uint4 u0 = ((const uint4*)er)[lane * 2];
        uint4 u1 = ((const uint4*)er)[lane * 2 + 1];
        __half hh[16];
        *(uint4*)hh = u0; *((uint4*)hh + 1) = u1;
        const float4* ls4 = (const float4*)(&g_label_sums[b][l][lane * 16]);
        float4 a0 = ls4[0], a1 = ls4[1], a2 = ls4[2], a3 = ls4[3];
        float lsv[16] = {a0.x,a0.y,a0.z,a0.w, a1.x,a1.y,a1.z,a1.w,
                         a2.x,a2.y,a2.z,a2.w, a3.x,a3.y,a3.z,a3.w};
        float dot = 0.f;
#pragma unroll
        for (int k = 0; k < 16; k++)
            dot = fmaf(__half2float(hh[k]), lsv[k], dot);
#pragma unroll
        for (int o = 16; o > 0; o >>= 1)
            dot += __shfl_xor_sync(0xffffffffu, dot, o);
        float C = cl - 1.f;
        float P = (dot - cl) * INV_T;
        loss = -(P - C * logf(g_S[w] + 1e-6f)) / C;
    }
    if (lane == 0) { lv[wslot] = loss; bv[wslot] = b; }
    __syncthreads();
    if (threadIdx.x == 0) {
        int b0 = bv[0], b1 = -1;
        float s0 = 0.f, s1 = 0.f;
#pragma unroll
        for (int i = 0; i < 8; i++) {
            if (bv[i] == b0) s0 += lv[i];
            else { b1 = bv[i]; s1 += lv[i]; }
        }
        atomicAdd(&g_supcon_sum[b0], s0);
        if (b1 >= 0) atomicAdd(&g_supcon_sum[b1], s1);
    }
}

// ---------------------------------------------------------------------------
// pd: per-image centroid pair-dots (16 blocks x 512, thread = dim)
// ---------------------------------------------------------------------------
__global__ void pd_kernel() {
    int b = blockIdx.x;
    int t = threadIdx.x;
    int lane = t & 31;
    float inv[NLBL];
#pragma unroll
    for (int l = 0; l < NLBL; l++) inv[l] = 1.f / fmaxf(g_cnt[b][l], 1.f);
    float raw[NLBL], m[NLBL];
    float sall = 0.f;
#pragma unroll
    for (int l = 0; l < NLBL; l++) {
        raw[l] = g_label_sums[b][l][t];
        m[l] = raw[l] * inv[l];
        sall += raw[l];
    }
    sall *= (1.f / (float)HW);
    float part[NPD];
    int k = 0;
#pragma unroll
    for (int l1 = 0; l1 < NLBL; l1++)
#pragma unroll
        for (int l2 = l1; l2 < NLBL; l2++) part[k++] = m[l1] * m[l2];
    part[28] = sall * sall;
#pragma unroll
    for (int i = 0; i < NPD; i++)
#pragma unroll
        for (int o = 16; o > 0; o >>= 1) part[i] += __shfl_xor_sync(0xffffffffu, part[i], o);
    __shared__ float acc[NPD];
    if (t < NPD) acc[t] = 0.f;
    __syncthreads();
    if (lane == 0) {
#pragma unroll
        for (int i = 0; i < NPD; i++) atomicAdd(&acc[i], part[i]);
    }
    __syncthreads();
    if (t < NPD) g_pd[b][t] = acc[t];
}

// ---------------------------------------------------------------------------
// finalize: pure scalar math. rn2 == 1 => var_l = 1 - ||mean_l||^2 etc.
// n_anchor derived analytically: sum of cnt_l over labels with cnt_l >= 2.
// ---------------------------------------------------------------------------
__global__ void finalize_kernel(const float* __restrict__ is_forged, float* __restrict__ out) {
    __shared__ float sc[BATCH], scv[BATCH], sp[BATCH], spv[BATCH], un[BATCH], unv[BATCH];
    int t = threadIdx.x;
    if (t < BATCH) {
        int b = t;
        float pd[NPD];
#pragma unroll
        for (int i = 0; i < NPD; i++) pd[i] = g_pd[b][i];
        float cnt[NLBL], cn[NLBL];
#pragma unroll
        for (int l = 0; l < NLBL; l++) {
            cnt[l] = g_cnt[b][l];
            cn[l] = pd[PD(l, l)];
        }
        float na = 0.f;
#pragma unroll
        for (int l = 0; l < NLBL; l++) if (cnt[l] >= 2.f) na += cnt[l];
        float supcon = g_supcon_sum[b] / fmaxf(na, 1.f);
        float supcon_valid = (na > 0.f) ? 1.f : 0.f;

        float terms = 0.f, npairs = 0.f;
        int npresent = 0;
#pragma unroll
        for (int l = 0; l < NLBL; l++) if (cnt[l] > 0.f) npresent++;
#pragma unroll
        for (int l1 = 0; l1 < NLBL; l1++)
#pragma unroll
            for (int l2 = l1 + 1; l2 < NLBL; l2++) {
                if (cnt[l1] > 0.f && cnt[l2] > 0.f) {
                    float sq = cn[l1] + cn[l2] - 2.f * pd[PD(l1, l2)];
                    float dd = sqrtf(fmaxf(sq, 0.f));
                    terms += fmaxf(SEPM - dd, 0.f);
                    npairs += 1.f;
                }
            }
        float sep = terms / fmaxf(npairs, 1.f);
        float sep_valid = (npresent >= 2) ? 1.f : 0.f;

        float uni, univ;
        if (is_forged[b] >= 0.5f) {
            float inst = 0.f, nl = 0.f;
#pragma unroll
            for (int l = 0; l < NLBL; l++) {
                float var = 1.0f - cn[l];      // q_l/cnt_l == 1 (unit-norm rows)
                if (cnt[l] >= 2.f && var > UNITH) { inst += var - UNITH; nl += 1.f; }
            }
            uni = inst / fmaxf(nl, 1.f);
            univ = (nl > 0.f) ? 1.f : 0.f;
        } else {
            float var_all = 1.0f - pd[28];     // q_all/HW == 1
            uni = (var_all > UNITH) ? (var_all - UNITH) : 0.f;
            univ = (var_all > UNITH) ? 1.f : 0.f;
        }

        sc[b] = supcon * supcon_valid; scv[b] = supcon_valid;
        sp[b] = sep * sep_valid;       spv[b] = sep_valid;
        un[b] = uni * univ;            unv[b] = univ;
    }
    __syncthreads();
    if (t == 0) {
        float a = 0.f, av = 0.f, s2 = 0.f, sv = 0.f, u = 0.f, uv = 0.f;
        for (int b = 0; b < BATCH; b++) {
            a += sc[b]; av += scv[b];
            s2 += sp[b]; sv += spv[b];
            u += un[b]; uv += unv[b];
        }
        float supcon = (av > 0.f) ? a / fmaxf(av, 1.f) : 0.f;
        float sep = (sv > 0.f) ? s2 / fmaxf(sv, 1.f) : 0.f;
        float uni = (uv > 0.f) ? u / fmaxf(uv, 1.f) : 0.f;
        out[0] = 1.0f * supcon + 0.5f * sep + 0.5f * uni;
    }
}

// ---------------------------------------------------------------------------
extern "C" void kernel_launch(void* const* d_in, const int* in_sizes, int n_in,
                              void* d_out, int out_size) {
    const float* emb   = (const float*)d_in[0];   // (16,33,33,512) f32
    const float* masks = (const float*)d_in[1];   // (16,6,33,33) f32
    const float* isf   = (const float*)d_in[2];   // (16,) f32
    float* out = (float*)d_out;

    cudaFuncSetAttribute(supcon_mma_kernel,
                         cudaFuncAttributeMaxDynamicSharedMemorySize, SM_TOTAL);

    prepcvt_kernel<<<PBLK + CVTBLK, 256>>>(masks, emb);                // 0
    labels_kernel<<<(BATCH * HW + 255) / 256, 256>>>(masks);           // 1
    centroid_kernel<<<dim3(CCHUNK, NLBL, BATCH), 512>>>();             // 2
    supcon_mma_kernel<<<dim3(NTILEPAIRS, BATCH), 512, SM_TOTAL>>>();   // 3 (ncu slot)
    rowloss_kernel<<<RLBLK, 256>>>();                                  // 4
    pd_kernel<<<BATCH, 512>>>();                                       // 5
    finalize_kernel<<<1, 32>>>(isf, out);                              // 6
}

// round 17
// speedup vs baseline: 1.9231x; 1.0590x over previous
#include <cuda_runtime.h>
#include <cuda_fp16.h>
#include <cstdint>
#include <math.h>

#define BATCH 16
#define NMASK 6
#define HW 1089
#define DIM 512
#define NLBL 7
#define INV_T (1.0f/0.07f)
#define SEPM 2.0f
#define UNITH 0.1f

#define CTILES 9          // ceil(1089/128)
#define NTILEPAIRS 45     // CTILES*(CTILES+1)/2
#define NPD 29            // 28 pair-dots + ||mean_all||^2

// ---- smem layout for supcon_mma (dynamic) ----
#define SM_ROWS 0                 // 128 floats (row S accum)
#define SM_COLS 512               // 128 floats (col S accum)
#define SM_BUF  1024
#define MATSZ   16384             // 128 rows x 64 fp16 (128B/row)
#define STAGESZ (2*MATSZ)         // A,B = 32KB
#define NSTAGE  3
#define SM_TOTAL (SM_BUF + NSTAGE*STAGESZ)   // 99328 -> 2 CTAs/SM

// ---- scratch (device globals: allocation-free) ----
__device__ float g_label_sums[BATCH][NLBL][DIM];
__device__ float g_cnt[BATCH][NLBL];
__device__ float g_supcon_sum[BATCH];
__device__ float g_pd[BATCH][NPD];
__device__ int   g_labels[BATCH * HW];
__device__ float g_S[BATCH * HW];
__device__ __align__(16) __half g_h[(size_t)BATCH * HW * DIM];

// ================= helpers =================
__device__ __forceinline__ uint32_t smem_u32(const void* p) {
    uint32_t a;
    asm("{ .reg .u64 t; cvta.to.shared.u64 t, %1; cvt.u32.u64 %0, t; }" : "=r"(a) : "l"(p));
    return a;
}
__device__ __forceinline__ void ldsm4(uint32_t* r, uint32_t addr) {
    asm volatile("ldmatrix.sync.aligned.m8n8.x4.shared.b16 {%0,%1,%2,%3}, [%4];"
                 : "=r"(r[0]), "=r"(r[1]), "=r"(r[2]), "=r"(r[3]) : "r"(addr));
}
__device__ __forceinline__ void mma_f16(float* c, const uint32_t* a, const uint32_t* b) {
    asm volatile("mma.sync.aligned.m16n8k16.row.col.f32.f16.f16.f32 "
                 "{%0,%1,%2,%3}, {%4,%5,%6,%7}, {%8,%9}, {%0,%1,%2,%3};"
                 : "+f"(c[0]), "+f"(c[1]), "+f"(c[2]), "+f"(c[3])
                 : "r"(a[0]), "r"(a[1]), "r"(a[2]), "r"(a[3]), "r"(b[0]), "r"(b[1]));
}
__device__ __forceinline__ int PD(int a, int c) { return a * 7 - (a * (a + 1)) / 2 + c; }

// Fast exp on FMA/ALU pipes (no MUFU): mean-one-tuned Schraudolph.
__device__ __forceinline__ float fexp(float x) {
    return __int_as_float((int)(fmaf(x, 12102203.0f, 1064870693.0f)));
}

// ---------------------------------------------------------------------------
// cvt + zero (fused):
//   blocks [0,224): zero accumulators
//   blocks [224,4580): streaming fp32 -> fp16 conversion (rn2 == 1 exactly)
// NOTE: the reference's per-channel `active = sum(mask)>0` flag is provably
// redundant: mask>0.5 at a pixel implies channel sum>0, so hit == mask>0.5.
// ---------------------------------------------------------------------------
#define ZBLK 224
#define CVTBLK ((BATCH * HW * DIM) / (256 * 8))   // 4356
__global__ void cvt_kernel(const float* __restrict__ emb) {
    int blk = blockIdx.x;
    if (blk < ZBLK) {
        int i = blk * 256 + threadIdx.x;
        if (i < BATCH * HW) g_S[i] = 0.f;
        if (i < BATCH * NLBL * DIM) ((float*)g_label_sums)[i] = 0.f;
        if (i < BATCH * NLBL) ((float*)g_cnt)[i] = 0.f;
        if (i < BATCH) g_supcon_sum[i] = 0.f;
    } else {
        size_t i = ((size_t)(blk - ZBLK) * 256 + threadIdx.x) * 8;
        float4 v0 = *(const float4*)(emb + i);
        float4 v1 = *(const float4*)(emb + i + 4);
        __half hh[8];
        hh[0] = __float2half(v0.x); hh[1] = __float2half(v0.y);
        hh[2] = __float2half(v0.z); hh[3] = __float2half(v0.w);
        hh[4] = __float2half(v1.x); hh[5] = __float2half(v1.y);
        hh[6] = __float2half(v1.z); hh[7] = __float2half(v1.w);
        *(uint4*)(g_h + i) = *(uint4*)hh;
    }
}

// ---------------------------------------------------------------------------
// labels: hit == mask>0.5 (active flag provably redundant)
// ---------------------------------------------------------------------------
__global__ void labels_kernel(const float* __restrict__ masks) {
    int idx = blockIdx.x * blockDim.x + threadIdx.x;
    if (idx >= BATCH * HW) return;
    int b = idx / HW, n = idx - b * HW;
    const float* mb = masks + (size_t)b * NMASK * HW;
    int lbl = 0;
#pragma unroll
    for (int m = 0; m < NMASK; m++) {
        if (mb[(size_t)m * HW + n] > 0.5f) lbl = m + 1;
    }
    g_labels[idx] = lbl;
}

// ---------------------------------------------------------------------------
// centroids: compact-then-accumulate. Block = (chunk, label, image).
// ---------------------------------------------------------------------------
#define CCHUNK 2
#define CROWS 545          // ceil(1089/2)
__global__ void centroid_kernel() {
    __shared__ int slist[CROWS];
    __shared__ int scnt;
    int ch = blockIdx.x, l = blockIdx.y, b = blockIdx.z;
    int t = threadIdx.x;
    int r0 = ch * CROWS;
    int r1 = (r0 + CROWS < HW) ? r0 + CROWS : HW;
    if (t == 0) scnt = 0;
    __syncthreads();
    for (int n = r0 + t; n < r1; n += 512) {
        if (g_labels[b * HW + n] == l) slist[atomicAdd(&scnt, 1)] = n;
    }
    __syncthreads();
    int cnt = scnt;
    if (cnt == 0) return;
    const __half* fb = g_h + (size_t)b * HW * DIM;
    float acc = 0.f;
    int i = 0;
    for (; i + 4 <= cnt; i += 4) {
        float v0 = __half2float(fb[(size_t)slist[i + 0] * DIM + t]);
        float v1 = __half2float(fb[(size_t)slist[i + 1] * DIM + t]);
        float v2 = __half2float(fb[(size_t)slist[i + 2] * DIM + t]);
        float v3 = __half2float(fb[(size_t)slist[i + 3] * DIM + t]);
        acc += (v0 + v1) + (v2 + v3);
    }
    for (; i < cnt; i++)
        acc += __half2float(fb[(size_t)slist[i] * DIM + t]);
    atomicAdd(&g_label_sums[b][l][t], acc);
    if (t == 0) atomicAdd(&g_cnt[b][l], (float)cnt);
}

// ---------------------------------------------------------------------------
// supcon Gram tile via mma.sync fp16. S-ONLY epilogue (P/C analytic in
// rowloss). Diagonal tiles reuse the A buffer for B (half the loads).
// ---------------------------------------------------------------------------
__global__ __launch_bounds__(512, 2) void supcon_mma_kernel() {
    extern __shared__ char smem[];
    uint32_t sb = smem_u32(smem);
    int tid = threadIdx.x;
    int wid = tid >> 5, lane = tid & 31;
    int wr = wid >> 2, wc = wid & 3;            // 4x4 warp grid, 32x32 tiles
    int b = blockIdx.y;
    int idx = blockIdx.x, rt = 0;
    while (idx >= CTILES - rt) { idx -= CTILES - rt; rt++; }
    int ct = rt + idx;
    bool diag = (ct == rt);
    int row0 = rt * 128, col0 = ct * 128;

    float* rowS = (float*)(smem + SM_ROWS);
    float* colS = (float*)(smem + SM_COLS);
    if (tid < 128) { rowS[tid] = 0.f; colS[tid] = 0.f; }

    const __half* bp = g_h + (size_t)b * HW * DIM;
    uint32_t boff = diag ? 0u : (uint32_t)MATSZ;   // diag: B == A buffer

    // ---- cp.async stage loader: A (+B if !diag), 128B rows, xor swizzle ----
    auto load_stage = [&](int c, int buf) {
        uint32_t dst_base = sb + SM_BUF + buf * STAGESZ;
#pragma unroll
        for (int it = 0; it < 4; it++) {
            int mat = it >> 1;                   // 0 = A, 1 = B
            if (mat == 1 && diag) break;
            int idxm = tid + 512 * (it & 1);     // 0..1023
            int row = idxm >> 3, seg = idxm & 7;
            int grow = ((mat == 0) ? row0 : col0) + row;
            uint32_t sz = (grow < HW) ? 16u : 0u;
            int gcl = (grow < HW) ? grow : 0;
            const __half* src = bp + (size_t)gcl * DIM + c * 64 + seg * 8;
            uint32_t dst = dst_base + mat * MATSZ + row * 128 +
                           (((uint32_t)(seg * 16)) ^ (((uint32_t)row & 7u) << 4));
            asm volatile("cp.async.cg.shared.global [%0], [%1], 16, %2;"
                         :: "r"(dst), "l"(src), "r"(sz) : "memory");
        }
        asm volatile("cp.async.commit_group;" ::: "memory");
    };

    // fragment address components (128B rows, swizzle mask (row&7)<<4)
    int a_r = wr * 32 + (lane & 15);
    uint32_t a_xm = (((uint32_t)lane) & 7u) << 4;
    uint32_t a_kb = (uint32_t)((lane >> 4) * 16);
    int b_n = wc * 32 + ((lane >> 4) & 1) * 8 + (lane & 7);
    uint32_t b_xm = (((uint32_t)lane) & 7u) << 4;
    uint32_t b_kb = (uint32_t)(((lane >> 3) & 1) * 16);

    float acc[2][4][4];
#pragma unroll
    for (int mt = 0; mt < 2; mt++)
#pragma unroll
        for (int nt = 0; nt < 4; nt++)
#pragma unroll
            for (int e = 0; e < 4; e++) acc[mt][nt][e] = 0.f;

    load_stage(0, 0);
    load_stage(1, 1);
    for (int c = 0; c < 8; c++) {
        if (c < 7) asm volatile("cp.async.wait_group 1;" ::: "memory");
        else       asm volatile("cp.async.wait_group 0;" ::: "memory");
        __syncthreads();   // chunk c visible; all warps done with c-1's buffer
        if (c + 2 < 8) load_stage(c + 2, (c + 2) % NSTAGE);
        uint32_t stg = sb + SM_BUF + (c % NSTAGE) * STAGESZ;
#pragma unroll
        for (int ks = 0; ks < 4; ks++) {
            uint32_t ka = (((uint32_t)(ks * 32)) + a_kb) ^ a_xm;
            uint32_t ah[2][4];
#pragma unroll
            for (int mt = 0; mt < 2; mt++) {
                uint32_t ad = stg + (uint32_t)((a_r + mt * 16) * 128) + ka;
                ldsm4(ah[mt], ad);
            }
            uint32_t kb2 = (((uint32_t)(ks * 32)) + b_kb) ^ b_xm;
#pragma unroll
            for (int ntp = 0; ntp < 2; ntp++) {
                uint32_t bh4[4];
                uint32_t bd = stg + boff + (uint32_t)((b_n + ntp * 16) * 128) + kb2;
                ldsm4(bh4, bd);
#pragma unroll
                for (int mt = 0; mt < 2; mt++) {
                    mma_f16(acc[mt][2 * ntp],     ah[mt], &bh4[0]);
                    mma_f16(acc[mt][2 * ntp + 1], ah[mt], &bh4[2]);
                }
            }
        }
    }
    __syncthreads();

    // ---- S-only epilogue: rows via shfl(1,2); cols per-nt via shfl(4,8,16) ----
    int lr4 = lane >> 2;
    float S[4];
    int rloc[4];
#pragma unroll
    for (int q = 0; q < 4; q++) {
        rloc[q] = wr * 32 + (q >> 1) * 16 + (q & 1) * 8 + lr4;
        S[q] = 0.f;
    }
#pragma unroll
    for (int nt = 0; nt < 4; nt++) {
        int cl0 = wc * 32 + nt * 8 + (lane & 3) * 2;
        int cg0 = col0 + cl0, cg1 = cg0 + 1;
        bool v0 = cg0 < HW, v1 = cg1 < HW;
        float Sc0 = 0.f, Sc1 = 0.f;
#pragma unroll
        for (int mt = 0; mt < 2; mt++)
#pragma unroll
            for (int h = 0; h < 2; h++) {
                int q = mt * 2 + h;
                int rg = row0 + rloc[q];
                float e0 = fexp((acc[mt][nt][h * 2 + 0] - 1.0f) * INV_T);
                float e1 = fexp((acc[mt][nt][h * 2 + 1] - 1.0f) * INV_T);
                if (rg < HW && v0 && cg0 != rg) { S[q] += e0; Sc0 += e0; }
                if (rg < HW && v1 && cg1 != rg) { S[q] += e1; Sc1 += e1; }
            }
        if (!diag) {
#pragma unroll
            for (int o = 4; o <= 16; o <<= 1) {
                Sc0 += __shfl_xor_sync(0xffffffffu, Sc0, o);
                Sc1 += __shfl_xor_sync(0xffffffffu, Sc1, o);
            }
            if (lane < 4) {
                atomicAdd(&colS[cl0], Sc0);
                atomicAdd(&colS[cl0 + 1], Sc1);
            }
        }
    }
#pragma unroll
    for (int q = 0; q < 4; q++) {
#pragma unroll
        for (int o = 1; o <= 2; o <<= 1)
            S[q] += __shfl_xor_sync(0xffffffffu, S[q], o);
    }
    if ((lane & 3) == 0) {
#pragma unroll
        for (int q = 0; q < 4; q++) atomicAdd(&rowS[rloc[q]], S[q]);
    }
    __syncthreads();
    if (tid < 128) {
        int rg = row0 + tid;
        if (rg < HW) atomicAdd(&g_S[b * HW + rg], rowS[tid]);
    } else if (tid < 256 && !diag) {
        int j = tid - 128;
        int cg = col0 + j;
        if (cg < HW) atomicAdd(&g_S[b * HW + cg], colS[j]);
    }
}

// ---------------------------------------------------------------------------
// rowloss + pd (fused):
//   blocks [0,2178): one warp per row, analytic P/C, block-reduced atomics
//   blocks [2178,2194): per-image centroid pair-dots (256 thr, 2 dims each)
// ---------------------------------------------------------------------------
#define RLBLK ((BATCH * HW) / 8)   // 2178
__global__ void rowpd_kernel() {
    if (blockIdx.x < RLBLK) {
        __shared__ float lv[8];
        __shared__ int bv[8];
        int wslot = threadIdx.x >> 5;
        int w = blockIdx.x * 8 + wslot;
        int lane = threadIdx.x & 31;
        int b = w / HW;
        int l = g_labels[w];
        float cl = g_cnt[b][l];
        float loss = 0.f;
        if (cl >= 2.f) {
            const __half* er = g_h + (size_t)w * DIM;
            uint4 u0 = ((const uint4*)er)[lane * 2];
            uint4 u1 = ((const uint4*)er)[lane * 2 + 1];
            __half hh[16];
            *(uint4*)hh = u0; *((uint4*)hh + 1) = u1;
            const float4* ls4 = (const float4*)(&g_label_sums[b][l][lane * 16]);
            float4 a0 = ls4[0], a1 = ls4[1], a2 = ls4[2], a3 = ls4[3];
            float lsv[16] = {a0.x,a0.y,a0.z,a0.w, a1.x,a1.y,a1.z,a1.w,
                             a2.x,a2.y,a2.z,a2.w, a3.x,a3.y,a3.z,a3.w};
            float dot = 0.f;
#pragma unroll
            for (int k = 0; k < 16; k++)
                dot = fmaf(__half2float(hh[k]), lsv[k], dot);
#pragma unroll
            for (int o = 16; o > 0; o >>= 1)
                dot += __shfl_xor_sync(0xffffffffu, dot, o);
            float C = cl - 1.f;
            float P = (dot - cl) * INV_T;
            loss = -(P - C * logf(g_S[w] + 1e-6f)) / C;
        }
        if (lane == 0) { lv[wslot] = loss; bv[wslot] = b; }
        __syncthreads();
        if (threadIdx.x == 0) {
            int b0 = bv[0], b1 = -1;
            float s0 = 0.f, s1 = 0.f;
#pragma unroll
            for (int i = 0; i < 8; i++) {
                if (bv[i] == b0) s0 += lv[i];
                else { b1 = bv[i]; s1 += lv[i]; }
            }
            atomicAdd(&g_supcon_sum[b0], s0);
            if (b1 >= 0) atomicAdd(&g_supcon_sum[b1], s1);
        }
    } else {
        int b = blockIdx.x - RLBLK;
        int t = threadIdx.x;           // handles dims t and t+256
        int lane = t & 31;
        float inv[NLBL];
#pragma unroll
        for (int l = 0; l < NLBL; l++) inv[l] = 1.f / fmaxf(g_cnt[b][l], 1.f);
        float m0[NLBL], m1[NLBL];
        float sall0 = 0.f, sall1 = 0.f;
#pragma unroll
        for (int l = 0; l < NLBL; l++) {
            float r0 = g_label_sums[b][l][t];
            float r1 = g_label_sums[b][l][t + 256];
            m0[l] = r0 * inv[l]; m1[l] = r1 * inv[l];
            sall0 += r0; sall1 += r1;
        }
        sall0 *= (1.f / (float)HW);
        sall1 *= (1.f / (float)HW);
        float part[NPD];
        int k = 0;
#pragma unroll
        for (int l1 = 0; l1 < NLBL; l1++)
#pragma unroll
            for (int l2 = l1; l2 < NLBL; l2++)
                part[k++] = m0[l1] * m0[l2] + m1[l1] * m1[l2];
        part[28] = sall0 * sall0 + sall1 * sall1;
#pragma unroll
        for (int i = 0; i < NPD; i++)
#pragma unroll
            for (int o = 16; o > 0; o >>= 1)
                part[i] += __shfl_xor_sync(0xffffffffu, part[i], o);
        __shared__ float acc[NPD];
        if (t < NPD) acc[t] = 0.f;
        __syncthreads();
        if (lane == 0) {
#pragma unroll
            for (int i = 0; i < NPD; i++) atomicAdd(&acc[i], part[i]);
        }
        __syncthreads();
        if (t < NPD) g_pd[b][t] = acc[t];
    }
}

// ---------------------------------------------------------------------------
// finalize: pure scalar math. rn2 == 1 => var_l = 1 - ||mean_l||^2 etc.
// n_anchor analytic: sum of cnt_l over labels with cnt_l >= 2.
// ---------------------------------------------------------------------------
__global__ void finalize_kernel(const float* __restrict__ is_forged, float* __restrict__ out) {
    __shared__ float sc[BATCH], scv[BATCH], sp[BATCH], spv[BATCH], un[BATCH], unv[BATCH];
    int t = threadIdx.x;
    if (t < BATCH) {
        int b = t;
        float pd[NPD];
#pragma unroll
        for (int i = 0; i < NPD; i++) pd[i] = g_pd[b][i];
        float cnt[NLBL], cn[NLBL];
#pragma unroll
        for (int l = 0; l < NLBL; l++) {
            cnt[l] = g_cnt[b][l];
            cn[l] = pd[PD(l, l)];
        }
        float na = 0.f;
#pragma unroll
        for (int l = 0; l < NLBL; l++) if (cnt[l] >= 2.f) na += cnt[l];
        float supcon = g_supcon_sum[b] / fmaxf(na, 1.f);
        float supcon_valid = (na > 0.f) ? 1.f : 0.f;

        float terms = 0.f, npairs = 0.f;
        int npresent = 0;
#pragma unroll
        for (int l = 0; l < NLBL; l++) if (cnt[l] > 0.f) npresent++;
#pragma unroll
        for (int l1 = 0; l1 < NLBL; l1++)
#pragma unroll
            for (int l2 = l1 + 1; l2 < NLBL; l2++) {
                if (cnt[l1] > 0.f && cnt[l2] > 0.f) {
                    float sq = cn[l1] + cn[l2] - 2.f * pd[PD(l1, l2)];
                    float dd = sqrtf(fmaxf(sq, 0.f));
                    terms += fmaxf(SEPM - dd, 0.f);
                    npairs += 1.f;
                }
            }
        float sep = terms / fmaxf(npairs, 1.f);
        float sep_valid = (npresent >= 2) ? 1.f : 0.f;

        float uni, univ;
        if (is_forged[b] >= 0.5f) {
            float inst = 0.f, nl = 0.f;
#pragma unroll
            for (int l = 0; l < NLBL; l++) {
                float var = 1.0f - cn[l];      // q_l/cnt_l == 1 (unit-norm rows)
                if (cnt[l] >= 2.f && var > UNITH) { inst += var - UNITH; nl += 1.f; }
            }
            uni = inst / fmaxf(nl, 1.f);
            univ = (nl > 0.f) ? 1.f : 0.f;
        } else {
            float var_all = 1.0f - pd[28];     // q_all/HW == 1
            uni = (var_all > UNITH) ? (var_all - UNITH) : 0.f;
            univ = (var_all > UNITH) ? 1.f : 0.f;
        }

        sc[b] = supcon * supcon_valid; scv[b] = supcon_valid;
        sp[b] = sep * sep_valid;       spv[b] = sep_valid;
        un[b] = uni * univ;            unv[b] = univ;
    }
    __syncthreads();
    if (t == 0) {
        float a = 0.f, av = 0.f, s2 = 0.f, sv = 0.f, u = 0.f, uv = 0.f;
        for (int b = 0; b < BATCH; b++) {
            a += sc[b]; av += scv[b];
            s2 += sp[b]; sv += spv[b];
            u += un[b]; uv += unv[b];
        }
        float supcon = (av > 0.f) ? a / fmaxf(av, 1.f) : 0.f;
        float sep = (sv > 0.f) ? s2 / fmaxf(sv, 1.f) : 0.f;
        float uni = (uv > 0.f) ? u / fmaxf(uv, 1.f) : 0.f;
        out[0] = 1.0f * supcon + 0.5f * sep + 0.5f * uni;
    }
}

// ---------------------------------------------------------------------------
extern "C" void kernel_launch(void* const* d_in, const int* in_sizes, int n_in,
                              void* d_out, int out_size) {
    const float* emb   = (const float*)d_in[0];   // (16,33,33,512) f32
    const float* masks = (const float*)d_in[1];   // (16,6,33,33) f32
    const float* isf   = (const float*)d_in[2];   // (16,) f32
    float* out = (float*)d_out;

    cudaFuncSetAttribute(supcon_mma_kernel,
                         cudaFuncAttributeMaxDynamicSharedMemorySize, SM_TOTAL);

    cvt_kernel<<<ZBLK + CVTBLK, 256>>>(emb);                           // 0
    labels_kernel<<<(BATCH * HW + 255) / 256, 256>>>(masks);           // 1
    centroid_kernel<<<dim3(CCHUNK, NLBL, BATCH), 512>>>();             // 2
    supcon_mma_kernel<<<dim3(NTILEPAIRS, BATCH), 512, SM_TOTAL>>>();   // 3 (ncu slot)
    rowpd_kernel<<<RLBLK + BATCH, 256>>>();                            // 4
    finalize_kernel<<<1, 32>>>(isf, out);                              // 5
}